// round 15
// baseline (speedup 1.0000x reference)
#include <cuda_runtime.h>
#include <cuda_fp16.h>

// ---------------------------------------------------------------------------
// SigTKANDense: tw*x -> depth-2 signature -> GRKAN (softmax weights) ->
//               big KAN-linear over (B*S) rows -> scale by weights.
// B=64, S=1024, D=64, U=128, NB=8, SIG_DIM=4160.
// Levy-area signature; tf32 mma grkan1; fp16 mma (m16n8k16) main layer.
// ---------------------------------------------------------------------------

#define B_ 64
#define S_ 1024
#define D_ 64
#define U_ 128
#define SIGD_ 4160
#define NCHUNK_ 130    // 32-feature chunks (skip kernel)
#define NKC_ 260       // 16-feature k-chunks (grkan1 / g_part)

// scratch (no allocations allowed -> device globals)
__device__ float    g_A[B_ * 4096];               // A = sum_t w_t (x) w_{t+1}
__device__ float    g_sig[B_ * SIGD_];            // [b][4160]
__device__ float    g_part[NKC_ * B_ * U_];       // h1 partials [kc][b][u]
__device__ float    g_skip[B_ * U_];              // skip accumulator (atomics)
__device__ float    g_h2[B_ * U_];                // h2 accumulator (atomics)
__device__ float    g_feat1[B_ * 9 * U_];         // features of h1: [b][j][u]
__device__ float    g_weights[B_ * U_];           // softmax weights per batch
__device__ __align__(16) __half g_wkh[U_ * 640];  // main weights fp16 [u][640]

__device__ __forceinline__ float silu_exact(float x) {
    return x * (1.0f / (1.0f + __expf(-x)));
}

// fast silu: 1 MUFU via tanh.approx
__device__ __forceinline__ float silu_fast(float x) {
    float t;
    asm("tanh.approx.f32 %0, %1;" : "=f"(t) : "f"(0.5f * x));
    return 0.5f * x * (1.0f + t);
}

__device__ __forceinline__ unsigned cvt_tf32(float x) {
    unsigned r;
    asm("cvt.rna.tf32.f32 %0, %1;" : "=r"(r) : "f"(x));
    return r;
}

// closed-form uniform cubic B-spline: cell index + 4 weights (j = i, i-1, i-2, i-3)
__device__ __forceinline__ void bspline4(float x, int& i, float* w) {
    float xc = (x + 2.2f) * 2.5f;
    float fi = floorf(xc);
    i = (int)fi;
    float t = xc - fi;
    float t2 = t * t, t3 = t2 * t;
    float omt = 1.0f - t;
    w[0] = t3 * (1.0f / 6.0f);
    w[1] = (-3.0f * t3 + 3.0f * t2 + 3.0f * t + 1.0f) * (1.0f / 6.0f);
    w[2] = (3.0f * t3 - 6.0f * t2 + 4.0f) * (1.0f / 6.0f);
    w[3] = omt * omt * omt * (1.0f / 6.0f);
}

__device__ __forceinline__ void mma_tf32(float d[4],
                                         unsigned a0, unsigned a1,
                                         unsigned a2, unsigned a3,
                                         unsigned b0, unsigned b1) {
    asm("mma.sync.aligned.m16n8k8.row.col.f32.tf32.tf32.f32 "
        "{%0,%1,%2,%3},{%4,%5,%6,%7},{%8,%9},{%0,%1,%2,%3};"
        : "+f"(d[0]), "+f"(d[1]), "+f"(d[2]), "+f"(d[3])
        : "r"(a0), "r"(a1), "r"(a2), "r"(a3), "r"(b0), "r"(b1));
}

__device__ __forceinline__ void mma_f16(float d[4],
                                        unsigned a0, unsigned a1,
                                        unsigned a2, unsigned a3,
                                        unsigned b0, unsigned b1) {
    asm("mma.sync.aligned.m16n8k16.row.col.f32.f16.f16.f32 "
        "{%0,%1,%2,%3},{%4,%5,%6,%7},{%8,%9},{%0,%1,%2,%3};"
        : "+f"(d[0]), "+f"(d[1]), "+f"(d[2]), "+f"(d[3])
        : "r"(a0), "r"(a1), "r"(a2), "r"(a3), "r"(b0), "r"(b1));
}

// compute 10 fp16 feature slots [silu, b0..b7, 0] and store as 5 half2 words
__device__ __forceinline__ void feat10_store(unsigned* dst, float v) {
    float s[10];
    s[0] = silu_fast(v);
#pragma unroll
    for (int j = 1; j < 10; j++) s[j] = 0.0f;
    int ci; float wv[4];
    bspline4(v, ci, wv);
#pragma unroll
    for (int k = 0; k < 4; k++) {
        int j = ci - k;
        if ((unsigned)j < 8u) s[1 + j] = wv[k];
    }
#pragma unroll
    for (int w = 0; w < 5; w++) {
        __half2 h = __floats2half2_rn(s[2 * w], s[2 * w + 1]);
        dst[w] = *(unsigned*)&h;
    }
}

#define SFA_STRIDE 76    // grkan1 tf32 feature row stride
#define SWB1_STRIDE 72   // grkan1 weight row stride (64 cols used)
#define WS_ 84           // fp16 main row stride in 32-bit words (conflict-free)

extern __shared__ float dynsm[];

// ---------------------------------------------------------------------------
// K0: zero the accumulators (g_A, g_skip, g_h2)
// ---------------------------------------------------------------------------
#define ZTOT_ (B_ * 4096 + 2 * B_ * U_)
__global__ void zero_kernel() {
    int i = blockIdx.x * blockDim.x + threadIdx.x;
    if (i < B_ * 4096) g_A[i] = 0.0f;
    else if (i < B_ * 4096 + B_ * U_) g_skip[i - B_ * 4096] = 0.0f;
    else if (i < ZTOT_) g_h2[i - B_ * 4096 - B_ * U_] = 0.0f;
}

// ---------------------------------------------------------------------------
// K0a: pre-convert main KAN weights to fp16, layout [u][640] (k = f*10+j).
// grid 4 (fc), 256 threads; smem transpose for coalesced read+write.
// ---------------------------------------------------------------------------
__global__ void __launch_bounds__(256) preconv_main(const float* __restrict__ kan_base,
                                                    const float* __restrict__ kan_spline) {
    int fc = blockIdx.x;
    int t = threadIdx.x;
    __shared__ __half s[128 * 160];
#pragma unroll 4
    for (int it = 0; it < 80; it++) {
        int e = t + it * 256;       // 0..20479, u fastest
        int u = e & 127, k = e >> 7;
        int f = fc * 16 + k / 10;
        int j = k - (k / 10) * 10;
        float val = 0.0f;
        if (j == 0) val = kan_base[(size_t)f * U_ + u];
        else if (j < 9) val = kan_spline[((size_t)f * 8 + j - 1) * U_ + u];
        s[u * 160 + k] = __float2half_rn(val);
    }
    __syncthreads();
    const unsigned* sw = (const unsigned*)s;
    unsigned* dst = (unsigned*)g_wkh;
#pragma unroll 4
    for (int it = 0; it < 40; it++) {
        int off = t + it * 256;     // word offset 0..10239
        int u = off / 80, kw = off - u * 80;
        dst[u * 320 + fc * 80 + kw] = sw[off];
    }
}

// ---------------------------------------------------------------------------
// K1: A = sum_t w_t (x) w_{t+1}  (Levy-area form; no staging, no inner syncs)
// ---------------------------------------------------------------------------
__global__ void __launch_bounds__(256) sig_kernel(const float* __restrict__ x,
                                                  const float* __restrict__ tw) {
    int b = blockIdx.x;
    int chunk = blockIdx.y;
    int t0 = chunk * 128;
    int t1 = min(1023, t0 + 128);
    int nt = t1 - t0;
    __shared__ float rows[129 * 64];
    int tid = threadIdx.x;

    for (int idx = tid; idx < (nt + 1) * 64; idx += 256) {
        int r = idx >> 6, d = idx & 63;
        rows[idx] = tw[t0 + r] * x[(size_t)(b * S_ + t0 + r) * D_ + d];
    }
    __syncthreads();

    float acc[4][4];
#pragma unroll
    for (int a = 0; a < 4; a++)
#pragma unroll
        for (int e = 0; e < 4; e++) acc[a][e] = 0.0f;

    int tj = (tid & 15) * 4;
    int ti = (tid >> 4) * 4;

#pragma unroll 4
    for (int lt = 0; lt < nt; lt++) {
        float4 av = *(const float4*)&rows[lt * 64 + ti];
        float4 bv = *(const float4*)&rows[(lt + 1) * 64 + tj];
        float a4[4] = {av.x, av.y, av.z, av.w};
        float b4[4] = {bv.x, bv.y, bv.z, bv.w};
#pragma unroll
        for (int a = 0; a < 4; a++)
#pragma unroll
            for (int e = 0; e < 4; e++) acc[a][e] = fmaf(a4[a], b4[e], acc[a][e]);
    }

    float* Ab = g_A + (size_t)b * 4096;
#pragma unroll
    for (int a = 0; a < 4; a++)
#pragma unroll
        for (int e = 0; e < 4; e++)
            atomicAdd(&Ab[(ti + a) * 64 + (tj + e)], acc[a][e]);
}

// ---------------------------------------------------------------------------
// K1b: assemble signature from A (parallelized: grid (64 b, 4 i-quarters)).
//   S2[i][j] = 0.5(A[i][j]-A[j][i]) + 0.5(we_i we_j - w0_i w0_j)
//              - w0_i (we_j - w0_j),   S1 = we - w0.
// ---------------------------------------------------------------------------
__global__ void __launch_bounds__(256) sig2_kernel(const float* __restrict__ x,
                                                   const float* __restrict__ tw) {
    int b = blockIdx.x;
    int i0 = blockIdx.y * 16;
    int tid = threadIdx.x;
    __shared__ float sR[16][64];    // A[i0:i0+16, :]
    __shared__ float sC[64][17];    // A[:, i0:i0+16]
    __shared__ float w0s[64], wes[64];

    if (tid < 64) w0s[tid] = tw[0] * x[(size_t)(b * S_) * D_ + tid];
    else if (tid < 128) wes[tid - 64] = tw[1023] * x[(size_t)(b * S_ + 1023) * D_ + (tid - 64)];
    const float* Ab = g_A + (size_t)b * 4096;
#pragma unroll
    for (int t = 0; t < 4; t++) {
        int idx = tid + t * 256;
        int r = idx >> 6, c = idx & 63;
        sR[r][c] = Ab[(i0 + r) * 64 + c];
        int j = idx >> 4, il = idx & 15;
        sC[j][il] = Ab[j * 64 + i0 + il];
    }
    __syncthreads();

#pragma unroll
    for (int t = 0; t < 4; t++) {
        int idx = tid + t * 256;
        int il = idx >> 6, j = idx & 63;
        int i = i0 + il;
        float w0i = w0s[i], wei = wes[i];
        float w0j = w0s[j], wej = wes[j];
        float s2 = 0.5f * (sR[il][j] - sC[j][il])
                 + 0.5f * (wei * wej - w0i * w0j)
                 - w0i * (wej - w0j);
        g_sig[(size_t)b * SIGD_ + 64 + i * 64 + j] = s2;
    }
    if (blockIdx.y == 0 && tid < 64)
        g_sig[(size_t)b * SIGD_ + tid] = wes[tid] - w0s[tid];
}

// ---------------------------------------------------------------------------
// K2: GRKAN stage-1 h1 partials via tf32 mma.
// 520 CTAs = (260 k-chunks of 16 features) x (2 u-halves). M=64, N=64, K=144.
// ---------------------------------------------------------------------------
__global__ void __launch_bounds__(128) grkan1_kernel(const float* __restrict__ g1_base,
                                                     const float* __restrict__ g1_spline) {
    int bx = blockIdx.x;            // 0..519
    int kc = bx >> 1, nh = bx & 1;
    int f0 = kc * 16;
    int tid = threadIdx.x;
    int lane = tid & 31, warp = tid >> 5;
    int gid = lane >> 2, tg = lane & 3;
    unsigned* sfeat = (unsigned*)dynsm;                   // [64][SFA_STRIDE]
    unsigned* swb = (unsigned*)dynsm + 64 * SFA_STRIDE;   // [72][SWB1_STRIDE]
    __shared__ float sig_s[64][17];

    for (int idx = tid; idx < 64 * 16; idx += 128) {
        int bb = idx >> 4, fl = idx & 15;
        sig_s[bb][fl] = g_sig[(size_t)bb * SIGD_ + f0 + fl];
    }

    float d[8][4];
#pragma unroll
    for (int n = 0; n < 8; n++)
#pragma unroll
        for (int c = 0; c < 4; c++) d[n][c] = 0.0f;

    for (int sub = 0; sub < 2; sub++) {
        __syncthreads();
        // features: 64 rows x 8 feats = 512 tasks / 128 threads
#pragma unroll
        for (int t = 0; t < 4; t++) {
            int task = tid + t * 128;
            int row = task >> 3, fg = task & 7;
            float v = sig_s[row][sub * 8 + fg];
            unsigned* fp = sfeat + row * SFA_STRIDE + fg * 9;
            fp[0] = cvt_tf32(silu_exact(v));
#pragma unroll
            for (int j = 1; j <= 8; j++) fp[j] = 0u;
            int ci; float wv[4];
            bspline4(v, ci, wv);
#pragma unroll
            for (int k = 0; k < 4; k++) {
                int j = ci - k;
                if ((unsigned)j < 8u) fp[1 + j] = cvt_tf32(wv[k]);
            }
        }
        // stage weights: 72 k-rows x 16 float4 (64 u of this half)
#pragma unroll
        for (int t = 0; t < 9; t++) {
            int idx = tid + t * 128;
            int row = idx >> 4, c4 = idx & 15;
            int fl = row / 9, jj = row - fl * 9;
            int f = f0 + sub * 8 + fl;
            const float* src = (jj == 0) ? (g1_base + (size_t)f * U_ + nh * 64)
                                         : (g1_spline + (size_t)(f * 8 + jj - 1) * U_ + nh * 64);
            float4 v = *(const float4*)(src + c4 * 4);
            unsigned* dst = swb + row * SWB1_STRIDE + c4 * 4;
            dst[0] = cvt_tf32(v.x); dst[1] = cvt_tf32(v.y);
            dst[2] = cvt_tf32(v.z); dst[3] = cvt_tf32(v.w);
        }
        __syncthreads();
        int m0 = warp * 16;
#pragma unroll
        for (int kk = 0; kk < 9; kk++) {
            int kl = kk * 8;
            unsigned a0 = sfeat[(m0 + gid) * SFA_STRIDE + kl + tg];
            unsigned a1 = sfeat[(m0 + gid + 8) * SFA_STRIDE + kl + tg];
            unsigned a2 = sfeat[(m0 + gid) * SFA_STRIDE + kl + tg + 4];
            unsigned a3 = sfeat[(m0 + gid + 8) * SFA_STRIDE + kl + tg + 4];
#pragma unroll
            for (int nt = 0; nt < 8; nt++) {
                unsigned b0 = swb[(kl + tg) * SWB1_STRIDE + nt * 8 + gid];
                unsigned b1 = swb[(kl + tg + 4) * SWB1_STRIDE + nt * 8 + gid];
                mma_tf32(d[nt], a0, a1, a2, a3, b0, b1);
            }
        }
    }
    int b0r = warp * 16 + gid;
#pragma unroll
    for (int nt = 0; nt < 8; nt++) {
        int u0 = nh * 64 + nt * 8 + tg * 2;
        size_t base = (size_t)kc * (B_ * U_);
        *(float2*)&g_part[base + b0r * U_ + u0] = make_float2(d[nt][0], d[nt][1]);
        *(float2*)&g_part[base + (b0r + 8) * U_ + u0] = make_float2(d[nt][2], d[nt][3]);
    }
}

// ---------------------------------------------------------------------------
// K2b: skip = sig @ skip_w (fp32), weights staged in smem.
// ---------------------------------------------------------------------------
__global__ void __launch_bounds__(512) skip_kernel(const float* __restrict__ skip_w) {
    int cta = blockIdx.x;           // 0..129
    int f0 = cta * 32;
    int tid = threadIdx.x;
    int u = tid & 127, bh = tid >> 7;
    __shared__ float sig_s[32][65];
    __shared__ float sw[32][128];
    for (int idx = tid; idx < 64 * 32; idx += 512) {
        int bb = idx >> 5, fl = idx & 31;
        sig_s[fl][bb] = g_sig[(size_t)bb * SIGD_ + f0 + fl];
    }
#pragma unroll
    for (int t = 0; t < 8; t++) {
        int idx = tid + t * 512;
        int row = idx >> 7, uu = idx & 127;
        sw[row][uu] = skip_w[(size_t)(f0 + row) * U_ + uu];
    }
    __syncthreads();
    float acc[16];
#pragma unroll
    for (int b = 0; b < 16; b++) acc[b] = 0.0f;
#pragma unroll 4
    for (int f = 0; f < 32; f++) {
        float w = sw[f][u];
        const float* sp = &sig_s[f][bh * 16];
#pragma unroll
        for (int b = 0; b < 16; b++)
            acc[b] = fmaf(sp[b], w, acc[b]);
    }
#pragma unroll
    for (int b = 0; b < 16; b++)
        atomicAdd(&g_skip[(bh * 16 + b) * U_ + u], acc[b]);
}

// ---------------------------------------------------------------------------
// K3: reduce h1 partials (4-way split over 260 chunks) -> features of h1.
// ---------------------------------------------------------------------------
__global__ void __launch_bounds__(512) reduce_feat_kernel() {
    int b = blockIdx.x;
    int tid = threadIdx.x;
    int u = tid & 127, cg = tid >> 7;
    __shared__ float red[4][128];
    float h = 0.0f;
#pragma unroll 4
    for (int c = cg; c < NKC_; c += 4)
        h += g_part[((size_t)c * B_ + b) * U_ + u];
    red[cg][u] = h;
    __syncthreads();
    if (tid < 128) {
        float h1 = red[0][u] + red[1][u] + red[2][u] + red[3][u];
        g_feat1[((size_t)b * 9 + 0) * U_ + u] = silu_exact(h1);
#pragma unroll
        for (int j = 0; j < 8; j++)
            g_feat1[((size_t)b * 9 + 1 + j) * U_ + u] = 0.0f;
        int ci; float wv[4];
        bspline4(h1, ci, wv);
#pragma unroll
        for (int k = 0; k < 4; k++) {
            int j = ci - k;
            if ((unsigned)j < 8u)
                g_feat1[((size_t)b * 9 + 1 + j) * U_ + u] = wv[k];
        }
    }
}

// ---------------------------------------------------------------------------
// K4: h2 partials (k-split), atomics into g_h2.
// ---------------------------------------------------------------------------
__global__ void __launch_bounds__(128) h2_kernel(const float* __restrict__ g2_base,
                                                 const float* __restrict__ g2_spline) {
    int f0 = blockIdx.x * 4;
    int u = threadIdx.x;
    __shared__ float fk[9][4][64];
    for (int idx = u; idx < 9 * 4 * 64; idx += 128) {
        int j = idx >> 8, r = idx & 255;
        int fl = r >> 6, bb = r & 63;
        fk[j][fl][bb] = g_feat1[((size_t)bb * 9 + j) * U_ + f0 + fl];
    }
    __syncthreads();
    float acc[64];
#pragma unroll
    for (int b = 0; b < 64; b++) acc[b] = 0.0f;
#pragma unroll
    for (int fl = 0; fl < 4; fl++) {
#pragma unroll
        for (int j = 0; j < 9; j++) {
            float w = (j == 0) ? g2_base[(size_t)(f0 + fl) * U_ + u]
                               : g2_spline[(size_t)((f0 + fl) * 8 + j - 1) * U_ + u];
#pragma unroll
            for (int b = 0; b < 64; b++)
                acc[b] = fmaf(fk[j][fl][b], w, acc[b]);
        }
    }
#pragma unroll
    for (int b = 0; b < 64; b++) atomicAdd(&g_h2[b * U_ + u], acc[b]);
}

// ---------------------------------------------------------------------------
// K5: gate + layernorm + softmax -> g_weights
// ---------------------------------------------------------------------------
__global__ void __launch_bounds__(128) tail_kernel(const float* __restrict__ skip_b,
                                                   const float* __restrict__ gate_ws,
                                                   const float* __restrict__ gate_bs,
                                                   const float* __restrict__ gate_wv,
                                                   const float* __restrict__ gate_bv,
                                                   const float* __restrict__ ln_g,
                                                   const float* __restrict__ ln_b) {
    int b = blockIdx.x;
    int u = threadIdx.x;
    __shared__ float s_h2[128];
    __shared__ float red[16];

    s_h2[u] = g_h2[b * U_ + u];
    __syncthreads();

    float gs = gate_bs[u], gv = gate_bv[u];
#pragma unroll 4
    for (int f = 0; f < 128; f++) {
        float h = s_h2[f];
        gs = fmaf(h, gate_ws[(size_t)f * U_ + u], gs);
        gv = fmaf(h, gate_wv[(size_t)f * U_ + u], gv);
    }
    float pre = g_skip[b * U_ + u] + skip_b[u] +
                (1.0f / (1.0f + __expf(-gs))) * gv;

    float v1 = pre, v2 = pre * pre;
#pragma unroll
    for (int o = 16; o; o >>= 1) {
        v1 += __shfl_xor_sync(0xffffffffu, v1, o);
        v2 += __shfl_xor_sync(0xffffffffu, v2, o);
    }
    int w = u >> 5, l = u & 31;
    if (l == 0) { red[w] = v1; red[4 + w] = v2; }
    __syncthreads();
    float mean = (red[0] + red[1] + red[2] + red[3]) * (1.0f / 128.0f);
    float ms   = (red[4] + red[5] + red[6] + red[7]) * (1.0f / 128.0f);
    float var  = ms - mean * mean;
    float ln   = ln_g[u] * (pre - mean) * rsqrtf(var + 1e-3f) + ln_b[u];

    float m = ln;
#pragma unroll
    for (int o = 16; o; o >>= 1) m = fmaxf(m, __shfl_xor_sync(0xffffffffu, m, o));
    if (l == 0) red[8 + w] = m;
    __syncthreads();
    m = fmaxf(fmaxf(red[8], red[9]), fmaxf(red[10], red[11]));
    float e = __expf(ln - m);
    float se = e;
#pragma unroll
    for (int o = 16; o; o >>= 1) se += __shfl_xor_sync(0xffffffffu, se, o);
    if (l == 0) red[12 + w] = se;
    __syncthreads();
    se = red[12] + red[13] + red[14] + red[15];

    g_weights[b * U_ + u] = e / se;
}

// ---------------------------------------------------------------------------
// K6: main fused KAN layer via fp16 mma (m16n8k16), M=32/warp.
// CTA = 128 rows x 128 cols, K=640; 4 chunks of 160. 128 threads = 4 warps.
// ---------------------------------------------------------------------------
__global__ void __launch_bounds__(128) main_kernel(const float* __restrict__ x,
                                                   const float* __restrict__ tw,
                                                   float* __restrict__ out) {
    int cta = blockIdx.x;            // 512 CTAs
    int b = cta >> 3;
    int s0 = (cta & 7) << 7;         // 128 rows per CTA
    int tid = threadIdx.x;
    int lane = tid & 31, warp = tid >> 5;
    int gid = lane >> 2, tg = lane & 3;
    unsigned* sfeat = (unsigned*)dynsm;              // [128][WS_]
    unsigned* swb = (unsigned*)dynsm + 128 * WS_;    // [128][WS_]

    float d[2][16][4];
#pragma unroll
    for (int mt = 0; mt < 2; mt++)
#pragma unroll
        for (int n = 0; n < 16; n++)
#pragma unroll
            for (int c = 0; c < 4; c++) d[mt][n][c] = 0.0f;

    for (int fc = 0; fc < 4; fc++) {
        __syncthreads();
        // features: 128 rows x 16 feats = 2048 tasks / 128 threads
#pragma unroll
        for (int t = 0; t < 16; t++) {
            int task = tid + t * 128;
            int row = task >> 4, fg = task & 15;
            int f = fc * 16 + fg;
            float v = tw[s0 + row] * x[(size_t)(b * S_ + s0 + row) * D_ + f];
            feat10_store(sfeat + row * WS_ + fg * 5, v);
        }
        // stage fp16 weights: 128 u-rows x 20 uint4
        const uint4* wsrc = (const uint4*)g_wkh;
#pragma unroll
        for (int t = 0; t < 20; t++) {
            int idx = tid + t * 128;        // 0..2559
            int u = idx / 20, q = idx - u * 20;
            *(uint4*)(swb + u * WS_ + q * 4) = wsrc[u * 80 + fc * 20 + q];
        }
        __syncthreads();
        int m0 = warp * 32;
#pragma unroll
        for (int ks = 0; ks < 10; ks++) {
            int kw = ks * 8;
            unsigned a[2][4];
#pragma unroll
            for (int mt = 0; mt < 2; mt++) {
                int mr = m0 + mt * 16;
                a[mt][0] = sfeat[(mr + gid) * WS_ + kw + tg];
                a[mt][1] = sfeat[(mr + gid + 8) * WS_ + kw + tg];
                a[mt][2] = sfeat[(mr + gid) * WS_ + kw + 4 + tg];
                a[mt][3] = sfeat[(mr + gid + 8) * WS_ + kw + 4 + tg];
            }
#pragma unroll
            for (int nt = 0; nt < 16; nt++) {
                int ul = nt * 8 + gid;
                unsigned b0 = swb[ul * WS_ + kw + tg];
                unsigned b1 = swb[ul * WS_ + kw + 4 + tg];
                mma_f16(d[0][nt], a[0][0], a[0][1], a[0][2], a[0][3], b0, b1);
                mma_f16(d[1][nt], a[1][0], a[1][1], a[1][2], a[1][3], b0, b1);
            }
        }
    }

    // epilogue: scale by softmax weights and store
#pragma unroll
    for (int nt = 0; nt < 16; nt++) {
        int c0 = nt * 8 + tg * 2;
        float w0 = g_weights[b * U_ + c0];
        float w1 = g_weights[b * U_ + c0 + 1];
#pragma unroll
        for (int mt = 0; mt < 2; mt++) {
            int r0 = s0 + warp * 32 + mt * 16 + gid;
            size_t o0 = (size_t)(b * S_ + r0) * U_ + c0;
            *(float2*)&out[o0] = make_float2(d[mt][nt][0] * w0, d[mt][nt][1] * w1);
            size_t o1 = (size_t)(b * S_ + r0 + 8) * U_ + c0;
            *(float2*)&out[o1] = make_float2(d[mt][nt][2] * w0, d[mt][nt][3] * w1);
        }
    }
}

// ---------------------------------------------------------------------------
extern "C" void kernel_launch(void* const* d_in, const int* in_sizes, int n_in,
                              void* d_out, int out_size) {
    const float* x          = (const float*)d_in[0];
    const float* tw         = (const float*)d_in[1];
    const float* kan_base   = (const float*)d_in[2];
    const float* kan_spline = (const float*)d_in[3];
    const float* g1_base    = (const float*)d_in[4];
    const float* g1_spline  = (const float*)d_in[5];
    const float* g2_base    = (const float*)d_in[6];
    const float* g2_spline  = (const float*)d_in[7];
    const float* skip_w     = (const float*)d_in[8];
    const float* skip_b     = (const float*)d_in[9];
    const float* gate_ws    = (const float*)d_in[10];
    const float* gate_bs    = (const float*)d_in[11];
    const float* gate_wv    = (const float*)d_in[12];
    const float* gate_bv    = (const float*)d_in[13];
    const float* ln_g       = (const float*)d_in[14];
    const float* ln_b       = (const float*)d_in[15];
    float* out = (float*)d_out;

    const int G1_SMEM = (64 * SFA_STRIDE + 72 * SWB1_STRIDE) * 4;    // 40192
    const int MAIN_SMEM = 2 * 128 * WS_ * 4;                         // 86016
    cudaFuncSetAttribute(grkan1_kernel, cudaFuncAttributeMaxDynamicSharedMemorySize, G1_SMEM);
    cudaFuncSetAttribute(main_kernel, cudaFuncAttributeMaxDynamicSharedMemorySize, MAIN_SMEM);

    zero_kernel<<<(ZTOT_ + 255) / 256, 256>>>();
    preconv_main<<<4, 256>>>(kan_base, kan_spline);
    sig_kernel<<<dim3(B_, 8), 256>>>(x, tw);
    sig2_kernel<<<dim3(B_, 4), 256>>>(x, tw);
    grkan1_kernel<<<520, 128, G1_SMEM>>>(g1_base, g1_spline);
    skip_kernel<<<NCHUNK_, 512>>>(skip_w);
    reduce_feat_kernel<<<B_, 512>>>();
    h2_kernel<<<32, 128>>>(g2_base, g2_spline);
    tail_kernel<<<B_, 128>>>(skip_b, gate_ws, gate_bs, gate_wv, gate_bv, ln_g, ln_b);
    main_kernel<<<512, 128, MAIN_SMEM>>>(x, tw, out);
}

// round 17
// speedup vs baseline: 1.1238x; 1.1238x over previous
#include <cuda_runtime.h>
#include <cuda_bf16.h>

// ---------------------------------------------------------------------------
// SigTKANDense: tw*x -> depth-2 signature -> GRKAN (softmax weights) ->
//               big KAN-linear over (B*S) rows -> scale by weights.
// B=64, S=1024, D=64, U=128, NB=8, SIG_DIM=4160.
// tf32 mma.sync m16n8k8; closed-form B-spline; Levy-area signature.
// ---------------------------------------------------------------------------

#define B_ 64
#define S_ 1024
#define D_ 64
#define U_ 128
#define SIGD_ 4160
#define NCHUNK_ 130    // 32-feature chunks (skip kernel)
#define NKC_ 260       // 16-feature k-chunks (grkan1 / g_part)

// scratch (no allocations allowed -> device globals)
__device__ float    g_A[B_ * 4096];               // A = sum_t w_t (x) w_{t+1}
__device__ float    g_sig[B_ * SIGD_];            // [b][4160]
__device__ float    g_part[NKC_ * B_ * U_];       // h1 partials [kc][b][u]
__device__ float    g_skip[B_ * U_];              // skip accumulator (atomics)
__device__ float    g_h2[B_ * U_];                // h2 accumulator (atomics)
__device__ float    g_feat1[B_ * 9 * U_];         // features of h1: [b][j][u]
__device__ float    g_weights[B_ * U_];           // softmax weights per batch
__device__ unsigned g_wk[576 * U_];               // main KAN weights tf32 bits [f*9+j][u]

__device__ __forceinline__ float silu_exact(float x) {
    return x * (1.0f / (1.0f + __expf(-x)));
}

// fast silu: 1 MUFU via tanh.approx
__device__ __forceinline__ float silu_fast(float x) {
    float t;
    asm("tanh.approx.f32 %0, %1;" : "=f"(t) : "f"(0.5f * x));
    return 0.5f * x * (1.0f + t);
}

__device__ __forceinline__ unsigned cvt_tf32(float x) {
    unsigned r;
    asm("cvt.rna.tf32.f32 %0, %1;" : "=r"(r) : "f"(x));
    return r;
}

// closed-form uniform cubic B-spline: cell index + 4 weights (j = i, i-1, i-2, i-3)
__device__ __forceinline__ void bspline4(float x, int& i, float* w) {
    float xc = (x + 2.2f) * 2.5f;
    float fi = floorf(xc);
    i = (int)fi;
    float t = xc - fi;
    float t2 = t * t, t3 = t2 * t;
    float omt = 1.0f - t;
    w[0] = t3 * (1.0f / 6.0f);
    w[1] = (-3.0f * t3 + 3.0f * t2 + 3.0f * t + 1.0f) * (1.0f / 6.0f);
    w[2] = (3.0f * t3 - 6.0f * t2 + 4.0f) * (1.0f / 6.0f);
    w[3] = omt * omt * omt * (1.0f / 6.0f);
}

__device__ __forceinline__ void mma_tf32(float d[4],
                                         unsigned a0, unsigned a1,
                                         unsigned a2, unsigned a3,
                                         unsigned b0, unsigned b1) {
    asm("mma.sync.aligned.m16n8k8.row.col.f32.tf32.tf32.f32 "
        "{%0,%1,%2,%3},{%4,%5,%6,%7},{%8,%9},{%0,%1,%2,%3};"
        : "+f"(d[0]), "+f"(d[1]), "+f"(d[2]), "+f"(d[3])
        : "r"(a0), "r"(a1), "r"(a2), "r"(a3), "r"(b0), "r"(b1));
}

#define SFA_STRIDE 76    // sfeat row stride (conflict-free A frags)
#define SWB_STRIDE 136   // main weight row stride (conflict-free B frags)
#define SWB1_STRIDE 72   // grkan1 weight row stride (64 cols used)

extern __shared__ float dynsm[];

// ---------------------------------------------------------------------------
// K0: zero the accumulators (g_A, g_skip, g_h2)
// ---------------------------------------------------------------------------
#define ZTOT_ (B_ * 4096 + 2 * B_ * U_)
__global__ void zero_kernel() {
    int i = blockIdx.x * blockDim.x + threadIdx.x;
    if (i < B_ * 4096) g_A[i] = 0.0f;
    else if (i < B_ * 4096 + B_ * U_) g_skip[i - B_ * 4096] = 0.0f;
    else if (i < ZTOT_) g_h2[i - B_ * 4096 - B_ * U_] = 0.0f;
}

// ---------------------------------------------------------------------------
// K0a: pre-convert main KAN weights to tf32 bits, layout [f*9+j][u]
// ---------------------------------------------------------------------------
__global__ void preconv_kernel(const float* __restrict__ kan_base,
                               const float* __restrict__ kan_spline) {
    int idx = blockIdx.x * 256 + threadIdx.x;
    if (idx >= 576 * U_) return;
    int k = idx >> 7, u = idx & 127;
    int f = k / 9, jj = k - f * 9;
    float w = (jj == 0) ? kan_base[(size_t)f * U_ + u]
                        : kan_spline[(size_t)(f * 8 + jj - 1) * U_ + u];
    g_wk[idx] = cvt_tf32(w);
}

// ---------------------------------------------------------------------------
// K1: A = sum_t w_t (x) w_{t+1}  (Levy-area form; no staging, no inner syncs)
// grid (64 batches, 16 t-chunks of 64 steps), 256 threads, 4x4 reg tiles.
// ---------------------------------------------------------------------------
__global__ void __launch_bounds__(256) sig_kernel(const float* __restrict__ x,
                                                  const float* __restrict__ tw) {
    int b = blockIdx.x;
    int chunk = blockIdx.y;
    int t0 = chunk * 64;
    int t1 = min(1023, t0 + 64);
    int nt = t1 - t0;
    __shared__ float rows[65 * 64];
    int tid = threadIdx.x;

    for (int idx = tid; idx < (nt + 1) * 64; idx += 256) {
        int r = idx >> 6, d = idx & 63;
        rows[idx] = tw[t0 + r] * x[(size_t)(b * S_ + t0 + r) * D_ + d];
    }
    __syncthreads();

    float acc[4][4];
#pragma unroll
    for (int a = 0; a < 4; a++)
#pragma unroll
        for (int e = 0; e < 4; e++) acc[a][e] = 0.0f;

    int tj = (tid & 15) * 4;
    int ti = (tid >> 4) * 4;

#pragma unroll 4
    for (int lt = 0; lt < nt; lt++) {
        float4 av = *(const float4*)&rows[lt * 64 + ti];
        float4 bv = *(const float4*)&rows[(lt + 1) * 64 + tj];
        float a4[4] = {av.x, av.y, av.z, av.w};
        float b4[4] = {bv.x, bv.y, bv.z, bv.w};
#pragma unroll
        for (int a = 0; a < 4; a++)
#pragma unroll
            for (int e = 0; e < 4; e++) acc[a][e] = fmaf(a4[a], b4[e], acc[a][e]);
    }

    float* Ab = g_A + (size_t)b * 4096;
#pragma unroll
    for (int a = 0; a < 4; a++)
#pragma unroll
        for (int e = 0; e < 4; e++)
            atomicAdd(&Ab[(ti + a) * 64 + (tj + e)], acc[a][e]);
}

// ---------------------------------------------------------------------------
// K1b: assemble signature from A (parallelized: grid (64 b, 4 i-quarters)).
//   S2[i][j] = 0.5(A[i][j]-A[j][i]) + 0.5(we_i we_j - w0_i w0_j)
//              - w0_i (we_j - w0_j),   S1 = we - w0.
// ---------------------------------------------------------------------------
__global__ void __launch_bounds__(256) sig2_kernel(const float* __restrict__ x,
                                                   const float* __restrict__ tw) {
    int b = blockIdx.x;
    int i0 = blockIdx.y * 16;
    int tid = threadIdx.x;
    __shared__ float sR[16][64];    // A[i0:i0+16, :]
    __shared__ float sC[64][17];    // A[:, i0:i0+16]
    __shared__ float w0s[64], wes[64];

    if (tid < 64) w0s[tid] = tw[0] * x[(size_t)(b * S_) * D_ + tid];
    else if (tid < 128) wes[tid - 64] = tw[1023] * x[(size_t)(b * S_ + 1023) * D_ + (tid - 64)];
    const float* Ab = g_A + (size_t)b * 4096;
#pragma unroll
    for (int t = 0; t < 4; t++) {
        int idx = tid + t * 256;
        int r = idx >> 6, c = idx & 63;
        sR[r][c] = Ab[(i0 + r) * 64 + c];
        int j = idx >> 4, il = idx & 15;
        sC[j][il] = Ab[j * 64 + i0 + il];
    }
    __syncthreads();

#pragma unroll
    for (int t = 0; t < 4; t++) {
        int idx = tid + t * 256;
        int il = idx >> 6, j = idx & 63;
        int i = i0 + il;
        float w0i = w0s[i], wei = wes[i];
        float w0j = w0s[j], wej = wes[j];
        float s2 = 0.5f * (sR[il][j] - sC[j][il])
                 + 0.5f * (wei * wej - w0i * w0j)
                 - w0i * (wej - w0j);
        g_sig[(size_t)b * SIGD_ + 64 + i * 64 + j] = s2;
    }
    if (blockIdx.y == 0 && tid < 64)
        g_sig[(size_t)b * SIGD_ + tid] = wes[tid] - w0s[tid];
}

// ---------------------------------------------------------------------------
// K2: GRKAN stage-1 h1 partials via tf32 mma.
// 520 CTAs = (260 k-chunks of 16 features) x (2 u-halves). M=64, N=64, K=144.
// ---------------------------------------------------------------------------
__global__ void __launch_bounds__(128) grkan1_kernel(const float* __restrict__ g1_base,
                                                     const float* __restrict__ g1_spline) {
    int bx = blockIdx.x;            // 0..519
    int kc = bx >> 1, nh = bx & 1;
    int f0 = kc * 16;
    int tid = threadIdx.x;
    int lane = tid & 31, warp = tid >> 5;
    int gid = lane >> 2, tg = lane & 3;
    unsigned* sfeat = (unsigned*)dynsm;                   // [64][SFA_STRIDE]
    unsigned* swb = (unsigned*)dynsm + 64 * SFA_STRIDE;   // [72][SWB1_STRIDE]
    __shared__ float sig_s[64][17];

    for (int idx = tid; idx < 64 * 16; idx += 128) {
        int bb = idx >> 4, fl = idx & 15;
        sig_s[bb][fl] = g_sig[(size_t)bb * SIGD_ + f0 + fl];
    }

    float d[8][4];
#pragma unroll
    for (int n = 0; n < 8; n++)
#pragma unroll
        for (int c = 0; c < 4; c++) d[n][c] = 0.0f;

    for (int sub = 0; sub < 2; sub++) {
        __syncthreads();
        // features: 64 rows x 8 feats = 512 tasks / 128 threads
#pragma unroll
        for (int t = 0; t < 4; t++) {
            int task = tid + t * 128;
            int row = task >> 3, fg = task & 7;
            float v = sig_s[row][sub * 8 + fg];
            unsigned* fp = sfeat + row * SFA_STRIDE + fg * 9;
            fp[0] = cvt_tf32(silu_exact(v));
#pragma unroll
            for (int j = 1; j <= 8; j++) fp[j] = 0u;
            int ci; float wv[4];
            bspline4(v, ci, wv);
#pragma unroll
            for (int k = 0; k < 4; k++) {
                int j = ci - k;
                if ((unsigned)j < 8u) fp[1 + j] = cvt_tf32(wv[k]);
            }
        }
        // stage weights: 72 k-rows x 16 float4 (64 u of this half)
#pragma unroll
        for (int t = 0; t < 9; t++) {
            int idx = tid + t * 128;
            int row = idx >> 4, c4 = idx & 15;
            int fl = row / 9, jj = row - fl * 9;
            int f = f0 + sub * 8 + fl;
            const float* src = (jj == 0) ? (g1_base + (size_t)f * U_ + nh * 64)
                                         : (g1_spline + (size_t)(f * 8 + jj - 1) * U_ + nh * 64);
            float4 v = *(const float4*)(src + c4 * 4);
            unsigned* dst = swb + row * SWB1_STRIDE + c4 * 4;
            dst[0] = cvt_tf32(v.x); dst[1] = cvt_tf32(v.y);
            dst[2] = cvt_tf32(v.z); dst[3] = cvt_tf32(v.w);
        }
        __syncthreads();
        int m0 = warp * 16;
#pragma unroll
        for (int kk = 0; kk < 9; kk++) {
            int kl = kk * 8;
            unsigned a0 = sfeat[(m0 + gid) * SFA_STRIDE + kl + tg];
            unsigned a1 = sfeat[(m0 + gid + 8) * SFA_STRIDE + kl + tg];
            unsigned a2 = sfeat[(m0 + gid) * SFA_STRIDE + kl + tg + 4];
            unsigned a3 = sfeat[(m0 + gid + 8) * SFA_STRIDE + kl + tg + 4];
#pragma unroll
            for (int nt = 0; nt < 8; nt++) {
                unsigned b0 = swb[(kl + tg) * SWB1_STRIDE + nt * 8 + gid];
                unsigned b1 = swb[(kl + tg + 4) * SWB1_STRIDE + nt * 8 + gid];
                mma_tf32(d[nt], a0, a1, a2, a3, b0, b1);
            }
        }
    }
    int b0r = warp * 16 + gid;
#pragma unroll
    for (int nt = 0; nt < 8; nt++) {
        int u0 = nh * 64 + nt * 8 + tg * 2;
        size_t base = (size_t)kc * (B_ * U_);
        *(float2*)&g_part[base + b0r * U_ + u0] = make_float2(d[nt][0], d[nt][1]);
        *(float2*)&g_part[base + (b0r + 8) * U_ + u0] = make_float2(d[nt][2], d[nt][3]);
    }
}

// ---------------------------------------------------------------------------
// K2b: skip = sig @ skip_w (fp32), weights staged in smem.
// ---------------------------------------------------------------------------
__global__ void __launch_bounds__(512) skip_kernel(const float* __restrict__ skip_w) {
    int cta = blockIdx.x;           // 0..129
    int f0 = cta * 32;
    int tid = threadIdx.x;
    int u = tid & 127, bh = tid >> 7;
    __shared__ float sig_s[32][65];
    __shared__ float sw[32][128];
    for (int idx = tid; idx < 64 * 32; idx += 512) {
        int bb = idx >> 5, fl = idx & 31;
        sig_s[fl][bb] = g_sig[(size_t)bb * SIGD_ + f0 + fl];
    }
#pragma unroll
    for (int t = 0; t < 8; t++) {
        int idx = tid + t * 512;
        int row = idx >> 7, uu = idx & 127;
        sw[row][uu] = skip_w[(size_t)(f0 + row) * U_ + uu];
    }
    __syncthreads();
    float acc[16];
#pragma unroll
    for (int b = 0; b < 16; b++) acc[b] = 0.0f;
#pragma unroll 4
    for (int f = 0; f < 32; f++) {
        float w = sw[f][u];
        const float* sp = &sig_s[f][bh * 16];
#pragma unroll
        for (int b = 0; b < 16; b++)
            acc[b] = fmaf(sp[b], w, acc[b]);
    }
#pragma unroll
    for (int b = 0; b < 16; b++)
        atomicAdd(&g_skip[(bh * 16 + b) * U_ + u], acc[b]);
}

// ---------------------------------------------------------------------------
// K3: reduce h1 partials (4-way split over 260 chunks) -> features of h1.
// ---------------------------------------------------------------------------
__global__ void __launch_bounds__(512) reduce_feat_kernel() {
    int b = blockIdx.x;
    int tid = threadIdx.x;
    int u = tid & 127, cg = tid >> 7;
    __shared__ float red[4][128];
    float h = 0.0f;
#pragma unroll 4
    for (int c = cg; c < NKC_; c += 4)
        h += g_part[((size_t)c * B_ + b) * U_ + u];
    red[cg][u] = h;
    __syncthreads();
    if (tid < 128) {
        float h1 = red[0][u] + red[1][u] + red[2][u] + red[3][u];
        g_feat1[((size_t)b * 9 + 0) * U_ + u] = silu_exact(h1);
#pragma unroll
        for (int j = 0; j < 8; j++)
            g_feat1[((size_t)b * 9 + 1 + j) * U_ + u] = 0.0f;
        int ci; float wv[4];
        bspline4(h1, ci, wv);
#pragma unroll
        for (int k = 0; k < 4; k++) {
            int j = ci - k;
            if ((unsigned)j < 8u)
                g_feat1[((size_t)b * 9 + 1 + j) * U_ + u] = wv[k];
        }
    }
}

// ---------------------------------------------------------------------------
// K4: h2 partials (k-split), atomics into g_h2.
// ---------------------------------------------------------------------------
__global__ void __launch_bounds__(128) h2_kernel(const float* __restrict__ g2_base,
                                                 const float* __restrict__ g2_spline) {
    int f0 = blockIdx.x * 4;
    int u = threadIdx.x;
    __shared__ float fk[9][4][64];
    for (int idx = u; idx < 9 * 4 * 64; idx += 128) {
        int j = idx >> 8, r = idx & 255;
        int fl = r >> 6, bb = r & 63;
        fk[j][fl][bb] = g_feat1[((size_t)bb * 9 + j) * U_ + f0 + fl];
    }
    __syncthreads();
    float acc[64];
#pragma unroll
    for (int b = 0; b < 64; b++) acc[b] = 0.0f;
#pragma unroll
    for (int fl = 0; fl < 4; fl++) {
#pragma unroll
        for (int j = 0; j < 9; j++) {
            float w = (j == 0) ? g2_base[(size_t)(f0 + fl) * U_ + u]
                               : g2_spline[(size_t)((f0 + fl) * 8 + j - 1) * U_ + u];
#pragma unroll
            for (int b = 0; b < 64; b++)
                acc[b] = fmaf(fk[j][fl][b], w, acc[b]);
        }
    }
#pragma unroll
    for (int b = 0; b < 64; b++) atomicAdd(&g_h2[b * U_ + u], acc[b]);
}

// ---------------------------------------------------------------------------
// K5: gate + layernorm + softmax -> g_weights
// ---------------------------------------------------------------------------
__global__ void __launch_bounds__(128) tail_kernel(const float* __restrict__ skip_b,
                                                   const float* __restrict__ gate_ws,
                                                   const float* __restrict__ gate_bs,
                                                   const float* __restrict__ gate_wv,
                                                   const float* __restrict__ gate_bv,
                                                   const float* __restrict__ ln_g,
                                                   const float* __restrict__ ln_b) {
    int b = blockIdx.x;
    int u = threadIdx.x;
    __shared__ float s_h2[128];
    __shared__ float red[16];

    s_h2[u] = g_h2[b * U_ + u];
    __syncthreads();

    float gs = gate_bs[u], gv = gate_bv[u];
#pragma unroll 4
    for (int f = 0; f < 128; f++) {
        float h = s_h2[f];
        gs = fmaf(h, gate_ws[(size_t)f * U_ + u], gs);
        gv = fmaf(h, gate_wv[(size_t)f * U_ + u], gv);
    }
    float pre = g_skip[b * U_ + u] + skip_b[u] +
                (1.0f / (1.0f + __expf(-gs))) * gv;

    float v1 = pre, v2 = pre * pre;
#pragma unroll
    for (int o = 16; o; o >>= 1) {
        v1 += __shfl_xor_sync(0xffffffffu, v1, o);
        v2 += __shfl_xor_sync(0xffffffffu, v2, o);
    }
    int w = u >> 5, l = u & 31;
    if (l == 0) { red[w] = v1; red[4 + w] = v2; }
    __syncthreads();
    float mean = (red[0] + red[1] + red[2] + red[3]) * (1.0f / 128.0f);
    float ms   = (red[4] + red[5] + red[6] + red[7]) * (1.0f / 128.0f);
    float var  = ms - mean * mean;
    float ln   = ln_g[u] * (pre - mean) * rsqrtf(var + 1e-3f) + ln_b[u];

    float m = ln;
#pragma unroll
    for (int o = 16; o; o >>= 1) m = fmaxf(m, __shfl_xor_sync(0xffffffffu, m, o));
    if (l == 0) red[8 + w] = m;
    __syncthreads();
    m = fmaxf(fmaxf(red[8], red[9]), fmaxf(red[10], red[11]));
    float e = __expf(ln - m);
    float se = e;
#pragma unroll
    for (int o = 16; o; o >>= 1) se += __shfl_xor_sync(0xffffffffu, se, o);
    if (l == 0) red[12 + w] = se;
    __syncthreads();
    se = red[12] + red[13] + red[14] + red[15];

    g_weights[b * U_ + u] = e / se;
}

// ---------------------------------------------------------------------------
// K6: main fused KAN layer via tf32 mma, M=32 per warp, fast silu.
// CTA = 128 rows x 128 cols, K=576; 128 threads = 4 warps (warp -> 32 rows).
// ---------------------------------------------------------------------------
__global__ void __launch_bounds__(128) main_kernel(const float* __restrict__ x,
                                                   const float* __restrict__ tw,
                                                   float* __restrict__ out) {
    int cta = blockIdx.x;            // 512 CTAs
    int b = cta >> 3;
    int s0 = (cta & 7) << 7;         // 128 rows per CTA
    int tid = threadIdx.x;
    int lane = tid & 31, warp = tid >> 5;
    int gid = lane >> 2, tg = lane & 3;
    unsigned* sfeat = (unsigned*)dynsm;                        // [128][SFA_STRIDE]
    unsigned* swb = (unsigned*)dynsm + 128 * SFA_STRIDE;       // [72][SWB_STRIDE]

    float d[2][16][4];
#pragma unroll
    for (int mt = 0; mt < 2; mt++)
#pragma unroll
        for (int n = 0; n < 16; n++)
#pragma unroll
            for (int c = 0; c < 4; c++) d[mt][n][c] = 0.0f;

    for (int fc = 0; fc < 8; fc++) {
        __syncthreads();
        // features: 128 rows x 8 features = 1024 tasks / 128 threads
#pragma unroll
        for (int t = 0; t < 8; t++) {
            int task = tid + t * 128;
            int row = task >> 3, fg = task & 7;
            int f = fc * 8 + fg;
            float v = tw[s0 + row] * x[(size_t)(b * S_ + s0 + row) * D_ + f];
            unsigned* fp = sfeat + row * SFA_STRIDE + fg * 9;
            fp[0] = cvt_tf32(silu_fast(v));
#pragma unroll
            for (int j = 1; j <= 8; j++) fp[j] = 0u;
            int ci; float wv[4];
            bspline4(v, ci, wv);
#pragma unroll
            for (int k = 0; k < 4; k++) {
                int j = ci - k;
                if ((unsigned)j < 8u) fp[1 + j] = cvt_tf32(wv[k]);
            }
        }
        // stage pre-converted weights: 72 rows x 32 uint4 / 128 threads
        const uint4* wsrc = (const uint4*)(g_wk + fc * 72 * U_);
#pragma unroll
        for (int t = 0; t < 18; t++) {
            int idx = tid + t * 128;
            int row = idx >> 5, c4 = idx & 31;
            *(uint4*)(swb + row * SWB_STRIDE + c4 * 4) = wsrc[row * 32 + c4];
        }
        __syncthreads();
        int m0 = warp * 32;
#pragma unroll
        for (int kk = 0; kk < 9; kk++) {
            int kl = kk * 8;
            unsigned a[2][4];
#pragma unroll
            for (int mt = 0; mt < 2; mt++) {
                int mr = m0 + mt * 16;
                a[mt][0] = sfeat[(mr + gid) * SFA_STRIDE + kl + tg];
                a[mt][1] = sfeat[(mr + gid + 8) * SFA_STRIDE + kl + tg];
                a[mt][2] = sfeat[(mr + gid) * SFA_STRIDE + kl + tg + 4];
                a[mt][3] = sfeat[(mr + gid + 8) * SFA_STRIDE + kl + tg + 4];
            }
#pragma unroll
            for (int nt = 0; nt < 16; nt++) {
                unsigned b0 = swb[(kl + tg) * SWB_STRIDE + nt * 8 + gid];
                unsigned b1 = swb[(kl + tg + 4) * SWB_STRIDE + nt * 8 + gid];
                mma_tf32(d[0][nt], a[0][0], a[0][1], a[0][2], a[0][3], b0, b1);
                mma_tf32(d[1][nt], a[1][0], a[1][1], a[1][2], a[1][3], b0, b1);
            }
        }
    }

    // epilogue: scale by softmax weights and store
#pragma unroll
    for (int nt = 0; nt < 16; nt++) {
        int c0 = nt * 8 + tg * 2;
        float w0 = g_weights[b * U_ + c0];
        float w1 = g_weights[b * U_ + c0 + 1];
#pragma unroll
        for (int mt = 0; mt < 2; mt++) {
            int r0 = s0 + warp * 32 + mt * 16 + gid;
            size_t o0 = (size_t)(b * S_ + r0) * U_ + c0;
            *(float2*)&out[o0] = make_float2(d[mt][nt][0] * w0, d[mt][nt][1] * w1);
            size_t o1 = (size_t)(b * S_ + r0 + 8) * U_ + c0;
            *(float2*)&out[o1] = make_float2(d[mt][nt][2] * w0, d[mt][nt][3] * w1);
        }
    }
}

// ---------------------------------------------------------------------------
extern "C" void kernel_launch(void* const* d_in, const int* in_sizes, int n_in,
                              void* d_out, int out_size) {
    const float* x          = (const float*)d_in[0];
    const float* tw         = (const float*)d_in[1];
    const float* kan_base   = (const float*)d_in[2];
    const float* kan_spline = (const float*)d_in[3];
    const float* g1_base    = (const float*)d_in[4];
    const float* g1_spline  = (const float*)d_in[5];
    const float* g2_base    = (const float*)d_in[6];
    const float* g2_spline  = (const float*)d_in[7];
    const float* skip_w     = (const float*)d_in[8];
    const float* skip_b     = (const float*)d_in[9];
    const float* gate_ws    = (const float*)d_in[10];
    const float* gate_bs    = (const float*)d_in[11];
    const float* gate_wv    = (const float*)d_in[12];
    const float* gate_bv    = (const float*)d_in[13];
    const float* ln_g       = (const float*)d_in[14];
    const float* ln_b       = (const float*)d_in[15];
    float* out = (float*)d_out;

    const int G1_SMEM = (64 * SFA_STRIDE + 72 * SWB1_STRIDE) * 4;    // 40192
    const int MAIN_SMEM = (128 * SFA_STRIDE + 72 * SWB_STRIDE) * 4;  // 78080
    cudaFuncSetAttribute(grkan1_kernel, cudaFuncAttributeMaxDynamicSharedMemorySize, G1_SMEM);
    cudaFuncSetAttribute(main_kernel, cudaFuncAttributeMaxDynamicSharedMemorySize, MAIN_SMEM);

    zero_kernel<<<(ZTOT_ + 255) / 256, 256>>>();
    preconv_kernel<<<(576 * U_ + 255) / 256, 256>>>(kan_base, kan_spline);
    sig_kernel<<<dim3(B_, 16), 256>>>(x, tw);
    sig2_kernel<<<dim3(B_, 4), 256>>>(x, tw);
    grkan1_kernel<<<520, 128, G1_SMEM>>>(g1_base, g1_spline);
    skip_kernel<<<NCHUNK_, 512>>>(skip_w);
    reduce_feat_kernel<<<B_, 512>>>();
    h2_kernel<<<32, 128>>>(g2_base, g2_spline);
    tail_kernel<<<B_, 128>>>(skip_b, gate_ws, gate_bs, gate_wv, gate_bv, ln_g, ln_b);
    main_kernel<<<512, 128, MAIN_SMEM>>>(x, tw, out);
}